// round 14
// baseline (speedup 1.0000x reference)
#include <cuda_runtime.h>
#include <cuda_fp16.h>
#include <cstdint>
#include <math.h>

// ============================================================================
// Experts MLP via plain fp16 mma.sync GEMMs (fp32 accumulate).
// R14 = R13 + persistent-CTA GEMM: grid = #SMs, each CTA loops tiles; the
// next tile's 3 stage-fills are issued BEFORE the epilogue so the epilogue
// hides the prologue DRAM latency (prologue exposed once per CTA, not per tile).
// ============================================================================

#define E_ 8
#define T_ 4096
#define D_ 1024
#define H_ 2048

#define A_BYTES 16384              // 128 rows * 128B
#define STAGE   49152              // A(16K) + B(32K)
#define NSTAGE  3

__device__ __align__(256) __half g_x2[(size_t)32768 * 1024];
__device__ __align__(256) __half g_w1t[(size_t)8 * 2048 * 1024];
__device__ __align__(256) __half g_h2[(size_t)32768 * 2048];
__device__ __align__(256) __half g_w2t[(size_t)8 * 1024 * 2048];

__device__ __forceinline__ uint32_t smem_u32(const void* p) {
    uint32_t a;
    asm("{ .reg .u64 t; cvta.to.shared.u64 t, %1; cvt.u32.u64 %0, t; }"
        : "=r"(a) : "l"(p));
    return a;
}
__device__ __forceinline__ void cpa16(uint32_t dst, const void* src) {
    asm volatile("cp.async.cg.shared.global [%0], [%1], 16;" :: "r"(dst), "l"(src));
}
__device__ __forceinline__ void ldsm_x4(uint32_t* r, uint32_t addr) {
    asm volatile("ldmatrix.sync.aligned.m8n8.x4.shared.b16 {%0,%1,%2,%3}, [%4];"
                 : "=r"(r[0]), "=r"(r[1]), "=r"(r[2]), "=r"(r[3]) : "r"(addr));
}
__device__ __forceinline__ void mma_f16(float* c, const uint32_t* a,
                                        uint32_t b0, uint32_t b1) {
    asm volatile(
        "mma.sync.aligned.m16n8k16.row.col.f32.f16.f16.f32 "
        "{%0,%1,%2,%3}, {%4,%5,%6,%7}, {%8,%9}, {%0,%1,%2,%3};"
        : "+f"(c[0]), "+f"(c[1]), "+f"(c[2]), "+f"(c[3])
        : "r"(a[0]), "r"(a[1]), "r"(a[2]), "r"(a[3]), "r"(b0), "r"(b1));
}

// Branchless GELU (A&S 7.1.28 erf approx; validated rel_err in R13).
__device__ __forceinline__ float gelu_fast(float v) {
    float x = fabsf(v) * 0.70710678118654752f;
    float p = 1.0f + x * (0.0705230784f + x * (0.0422820123f
            + x * (0.0092705272f + x * (0.0001520143f
            + x * (0.0002765672f + x * 0.0000430638f)))));
    float p2 = p * p;
    float p4 = p2 * p2;
    float p8 = p4 * p4;
    float p16 = p8 * p8;
    float erf;
    asm("rcp.approx.f32 %0, %1;" : "=f"(erf) : "f"(p16));
    erf = 1.0f - erf;
    float cdf = fmaf(copysignf(erf, v), 0.5f, 0.5f);
    return v * cdf;
}

__device__ __forceinline__ uint32_t pk(__half a, __half b) {
    return (uint32_t)__half_as_ushort(a) | ((uint32_t)__half_as_ushort(b) << 16);
}

// ============================================================================
// merged prepass (R13, unchanged): x (16384 blks) | w1 (8192) | w2 (8192)
// ============================================================================
__device__ __forceinline__ void conv_w_tile(const float* __restrict__ we,
                                            __half* __restrict__ oe,
                                            float (*t)[65],
                                            int K, int N, int kb, int nb,
                                            int tid) {
    {
        const int r = tid >> 3;
        const int c0 = (tid & 7) * 8;
        const float* src = we + (size_t)(kb + r) * N + nb + c0;
        float4 v0 = *(const float4*)src;
        float4 v1 = *(const float4*)(src + 4);
        t[r][c0 + 0] = v0.x; t[r][c0 + 1] = v0.y; t[r][c0 + 2] = v0.z; t[r][c0 + 3] = v0.w;
        t[r][c0 + 4] = v1.x; t[r][c0 + 5] = v1.y; t[r][c0 + 6] = v1.z; t[r][c0 + 7] = v1.w;
    }
    __syncthreads();
    {
        const int nloc = tid >> 2;
        const int kq = (tid & 3) * 8;
        uint32_t o[4];
        #pragma unroll
        for (int j = 0; j < 4; j++)
            o[j] = pk(__float2half_rn(t[kq + 2 * j][nloc]),
                      __float2half_rn(t[kq + 2 * j + 1][nloc]));
        *(uint4*)(oe + (size_t)(nb + nloc) * K + kb + kq) =
            make_uint4(o[0], o[1], o[2], o[3]);
    }
    __syncthreads();
}

__global__ void prepass(const float* __restrict__ x,
                        const float* __restrict__ w1,
                        const float* __restrict__ w2,
                        __half* __restrict__ x2,
                        __half* __restrict__ w1t,
                        __half* __restrict__ w2t)
{
    __shared__ float t[32][65];
    const int bid = blockIdx.x;
    const int tid = threadIdx.x;

    if (bid < 16384) {
        size_t base = ((size_t)bid * 256 + tid) * 8;
        float4 v0 = *(const float4*)(x + base);
        float4 v1 = *(const float4*)(x + base + 4);
        uint4 o;
        o.x = pk(__float2half_rn(v0.x), __float2half_rn(v0.y));
        o.y = pk(__float2half_rn(v0.z), __float2half_rn(v0.w));
        o.z = pk(__float2half_rn(v1.x), __float2half_rn(v1.y));
        o.w = pk(__float2half_rn(v1.z), __float2half_rn(v1.w));
        *(uint4*)(x2 + base) = o;
    } else if (bid < 24576) {
        const int rem = bid - 16384;
        const int e = rem >> 10;
        const int within = rem & 1023;
        const int kb = (within & 31) * 32;
        const int nb = (within >> 5) * 64;
        conv_w_tile(w1 + (size_t)e * D_ * H_, w1t + (size_t)e * H_ * D_,
                    t, D_, H_, kb, nb, tid);
    } else {
        const int rem = bid - 24576;
        const int e = rem >> 10;
        const int within = rem & 1023;
        const int kb = (within & 63) * 32;
        const int nb = (within >> 6) * 64;
        conv_w_tile(w2 + (size_t)e * H_ * D_, w2t + (size_t)e * D_ * H_,
                    t, H_, D_, kb, nb, tid);
    }
}

// ============================================================================
// Persistent GEMM: grid = #SMs; tiles 128x256; next-tile fills hidden behind
// epilogue. Inner pipeline identical to R12 champion.
// ============================================================================
template <int EPI, int KR, int NB>
__global__ __launch_bounds__(256, 1)
void gemm_mma(const __half* __restrict__ A,
              const __half* __restrict__ B,
              const float* __restrict__ bias,
              float* __restrict__ OutF,
              __half* __restrict__ OutH,
              int numTiles)
{
    extern __shared__ __align__(1024) char sm[];
    __shared__ float s_bias[256];

    constexpr int NC = KR / 64;
    constexpr size_t gStride = (size_t)64 * KR;
    constexpr int TX = NB / 256;                 // tiles along N

    const int tid = threadIdx.x;
    const int wid = tid >> 5;
    const int lid = tid & 31;
    const int warp_m = wid >> 2;
    const int warp_n = wid & 3;
    const uint32_t smb = smem_u32(sm);

    const int r0 = tid >> 3, g0 = tid & 7;
    const uint32_t sO0 = (uint32_t)(r0 * 128 + ((g0 << 4) ^ ((r0 & 7) << 4)));

    const int lr = (lid & 7) + ((lid >> 3) & 1) * 8;
    const uint32_t lcol = ((lid >> 4) & 1) << 4;
    const uint32_t xr = (uint32_t)(lr & 7) << 4;
    const uint32_t arb0 = (uint32_t)(warp_m * 64 + lr) * 128;
    const uint32_t brb0 = (uint32_t)(warp_n * 64 + lr) * 128 + A_BYTES;

    uint32_t colq[4];
    #pragma unroll
    for (int q = 0; q < 4; q++) colq[q] = ((uint32_t)(q << 5) | lcol) ^ xr;

    const uint32_t stg0 = smb, stg1 = smb + STAGE, stg2 = smb + 2 * STAGE;

    // ---- per-tile mutable state ----
    const char* aCur;
    const char* bCur;
    int eT, colBaseT;
    size_t rowGlob0T;

    auto setTile = [&](int t) {
        const int perE = 32 * TX;                // (T_/128) * TX
        eT = t / perE;
        const int w = t - eT * perE;
        const int by = w / TX;
        const int bx = w - by * TX;
        colBaseT = bx * 256;
        rowGlob0T = (size_t)eT * T_ + by * 128;
        aCur = (const char*)(A + (rowGlob0T + r0) * (size_t)KR) + g0 * 16;
        bCur = (const char*)(B + ((size_t)eT * NB + colBaseT + r0) * (size_t)KR) + g0 * 16;
    };

    auto fill = [&](uint32_t sbase) {
        uint32_t sb = sbase + sO0;
        #pragma unroll
        for (int i = 0; i < 4; i++)
            cpa16(sb + i * 4096, aCur + i * gStride);
        #pragma unroll
        for (int i = 0; i < 8; i++)
            cpa16(sb + A_BYTES + i * 4096, bCur + i * gStride);
        asm volatile("cp.async.commit_group;" ::: "memory");
        aCur += 128; bCur += 128;
    };
    auto commit_empty = [&]() {
        asm volatile("cp.async.commit_group;" ::: "memory");
    };

    auto ldA = [&](uint32_t st, uint32_t col, uint32_t (&fr)[4][4]) {
        #pragma unroll
        for (int f = 0; f < 4; f++)
            ldsm_x4(fr[f], st + arb0 + f * 2048 + col);
    };
    auto ldB = [&](uint32_t st, uint32_t col, uint32_t (&fr)[4][4]) {
        #pragma unroll
        for (int g = 0; g < 4; g++)
            ldsm_x4(fr[g], st + brb0 + g * 2048 + col);
    };

    float acc[4][8][4];
    auto mmaT = [&](const uint32_t (&a)[4][4], const uint32_t (&b)[4][4]) {
        #pragma unroll
        for (int m = 0; m < 4; m++)
            #pragma unroll
            for (int n = 0; n < 8; n++)
                mma_f16(acc[m][n], a[m], b[n >> 1][n & 1], b[n >> 1][2 + (n & 1)]);
    };

    int t = blockIdx.x;
    if (t >= numTiles) return;
    setTile(t);
    fill(stg0); fill(stg1); fill(stg2);

    while (true) {
        // bias for the tile we are about to compute
        const float bv = bias[(size_t)eT * NB + colBaseT + tid];

        asm volatile("cp.async.wait_group 2;" ::: "memory");
        __syncthreads();                       // also orders prior epilogue reads
        s_bias[tid] = bv;

        #pragma unroll
        for (int m = 0; m < 4; m++)
            #pragma unroll
            for (int n = 0; n < 8; n++)
                #pragma unroll
                for (int q = 0; q < 4; q++)
                    acc[m][n][q] = 0.0f;

        uint32_t st0 = stg0, st1 = stg1, st2 = stg2;
        uint32_t aF[2][4][4], bF[2][4][4];
        ldA(st0, colq[0], aF[0]);
        ldB(st0, colq[0], bF[0]);

        #pragma unroll 1
        for (int c = 0; c < NC - 1; c++) {
            const uint32_t st = st0;

            ldA(st, colq[1], aF[1]);
            ldB(st, colq[1], bF[1]);
            mmaT(aF[0], bF[0]);                // q0

            ldA(st, colq[2], aF[0]);
            ldB(st, colq[2], bF[0]);
            mmaT(aF[1], bF[1]);                // q1

            ldA(st, colq[3], aF[1]);
            ldB(st, colq[3], bF[1]);
            mmaT(aF[0], bF[0]);                // q2

            asm volatile("cp.async.wait_group 1;" ::: "memory");
            __syncthreads();
            if (c + 3 < NC) fill(st); else commit_empty();

            ldA(st1, colq[0], aF[0]);          // next chunk q0 prefetch
            mmaT(aF[1], bF[1]);                // q3 (register-only)
            ldB(st1, colq[0], bF[0]);

            uint32_t tmp = st0; st0 = st1; st1 = st2; st2 = tmp;
        }

        // final chunk
        {
            const uint32_t st = st0;
            ldA(st, colq[1], aF[1]);
            ldB(st, colq[1], bF[1]);
            mmaT(aF[0], bF[0]);
            ldA(st, colq[2], aF[0]);
            ldB(st, colq[2], bF[0]);
            mmaT(aF[1], bF[1]);
            ldA(st, colq[3], aF[1]);
            ldB(st, colq[3], bF[1]);
            mmaT(aF[0], bF[0]);
            mmaT(aF[1], bF[1]);
        }
        __syncthreads();                       // all LDSM of this tile done

        // ---- save epilogue base, advance tile, issue next-tile fills ----
        __half* outH = (EPI == 1)
            ? OutH + rowGlob0T * (size_t)NB + colBaseT : (OutH = nullptr, nullptr);
        float* outF = (EPI == 0)
            ? OutF + rowGlob0T * (size_t)NB + colBaseT : nullptr;

        t += gridDim.x;
        const bool more = (t < numTiles);
        if (more) {
            setTile(t);
            fill(stg0); fill(stg1); fill(stg2);   // hidden behind epilogue
        }

        // ---- epilogue (uses saved base only) ----
        #pragma unroll
        for (int m = 0; m < 4; m++) {
            const int rOff = warp_m * 64 + m * 16 + (lid >> 2);
            #pragma unroll
            for (int n = 0; n < 8; n++) {
                const int cl = warp_n * 64 + n * 8 + (lid & 3) * 2;
                const float b0 = s_bias[cl], b1 = s_bias[cl + 1];
                #pragma unroll
                for (int h = 0; h < 2; h++) {
                    float v0 = acc[m][n][2 * h + 0] + b0;
                    float v1 = acc[m][n][2 * h + 1] + b1;
                    const size_t rowOff = (size_t)(rOff + h * 8) * NB + cl;
                    if (EPI == 1) {
                        v0 = gelu_fast(v0); v1 = gelu_fast(v1);
                        *(uint32_t*)(outH + rowOff) =
                            pk(__float2half_rn(v0), __float2half_rn(v1));
                    } else {
                        *(float2*)(outF + rowOff) = make_float2(v0, v1);
                    }
                }
            }
        }

        if (!more) break;
    }
}

// ============================================================================
extern "C" void kernel_launch(void* const* d_in, const int* in_sizes, int n_in,
                              void* d_out, int out_size)
{
    (void)in_sizes; (void)n_in; (void)out_size;
    const float* x  = (const float*)d_in[0];
    const float* w1 = (const float*)d_in[1];
    const float* b1 = (const float*)d_in[2];
    const float* w2 = (const float*)d_in[3];
    const float* b2 = (const float*)d_in[4];
    float* out = (float*)d_out;

    __half *x2, *w1t, *h2, *w2t;
    cudaGetSymbolAddress((void**)&x2,  g_x2);
    cudaGetSymbolAddress((void**)&w1t, g_w1t);
    cudaGetSymbolAddress((void**)&h2,  g_h2);
    cudaGetSymbolAddress((void**)&w2t, g_w2t);

    int dev = 0, nsm = 148;
    cudaGetDevice(&dev);
    cudaDeviceGetAttribute(&nsm, cudaDevAttrMultiProcessorCount, dev);

    const int SMEM = NSTAGE * STAGE;   // 147456
    cudaFuncSetAttribute((const void*)gemm_mma<1, D_, H_>,
                         cudaFuncAttributeMaxDynamicSharedMemorySize, SMEM);
    cudaFuncSetAttribute((const void*)gemm_mma<0, H_, D_>,
                         cudaFuncAttributeMaxDynamicSharedMemorySize, SMEM);

    // merged prepass
    prepass<<<32768, 256>>>(x, w1, w2, x2, w1t, w2t);

    // GEMM1: K=1024, N=2048; 2048 tiles, persistent over nsm CTAs
    const int tiles1 = E_ * (T_ / 128) * (H_ / 256);
    gemm_mma<1, D_, H_><<<nsm < tiles1 ? nsm : tiles1, 256, SMEM>>>(
        x2, w1t, b1, nullptr, h2, tiles1);

    // GEMM2: K=2048, N=1024; 1024 tiles
    const int tiles2 = E_ * (T_ / 128) * (D_ / 256);
    gemm_mma<0, H_, D_><<<nsm < tiles2 ? nsm : tiles2, 256, SMEM>>>(
        h2, w2t, b2, out, nullptr, tiles2);
}

// round 15
// speedup vs baseline: 1.0093x; 1.0093x over previous
#include <cuda_runtime.h>
#include <cuda_fp16.h>
#include <cstdint>
#include <math.h>

// ============================================================================
// Experts MLP via plain fp16 mma.sync GEMMs (fp32 accumulate).
// R15 = R13 champion with:
//   (1) 4-stage cp.async pipeline, 4-fill prologue, wait_group 2 (one extra
//       chunk-duration of latency slack per fill; loop cadence unchanged)
//   (2) __ldcs on prepass inputs (read-once -> evict-first)
//   (3) st.global.cs on GEMM2 output (write-once -> don't pollute L2)
// ============================================================================

#define E_ 8
#define T_ 4096
#define D_ 1024
#define H_ 2048

#define A_BYTES 16384              // 128 rows * 128B
#define STAGE   49152              // A(16K) + B(32K)
#define NSTAGE  4

__device__ __align__(256) __half g_x2[(size_t)32768 * 1024];
__device__ __align__(256) __half g_w1t[(size_t)8 * 2048 * 1024];
__device__ __align__(256) __half g_h2[(size_t)32768 * 2048];
__device__ __align__(256) __half g_w2t[(size_t)8 * 1024 * 2048];

__device__ __forceinline__ uint32_t smem_u32(const void* p) {
    uint32_t a;
    asm("{ .reg .u64 t; cvta.to.shared.u64 t, %1; cvt.u32.u64 %0, t; }"
        : "=r"(a) : "l"(p));
    return a;
}
__device__ __forceinline__ void cpa16(uint32_t dst, const void* src) {
    asm volatile("cp.async.cg.shared.global [%0], [%1], 16;" :: "r"(dst), "l"(src));
}
__device__ __forceinline__ void ldsm_x4(uint32_t* r, uint32_t addr) {
    asm volatile("ldmatrix.sync.aligned.m8n8.x4.shared.b16 {%0,%1,%2,%3}, [%4];"
                 : "=r"(r[0]), "=r"(r[1]), "=r"(r[2]), "=r"(r[3]) : "r"(addr));
}
__device__ __forceinline__ void mma_f16(float* c, const uint32_t* a,
                                        uint32_t b0, uint32_t b1) {
    asm volatile(
        "mma.sync.aligned.m16n8k16.row.col.f32.f16.f16.f32 "
        "{%0,%1,%2,%3}, {%4,%5,%6,%7}, {%8,%9}, {%0,%1,%2,%3};"
        : "+f"(c[0]), "+f"(c[1]), "+f"(c[2]), "+f"(c[3])
        : "r"(a[0]), "r"(a[1]), "r"(a[2]), "r"(a[3]), "r"(b0), "r"(b1));
}

// Branchless GELU (A&S 7.1.28 erf approx; validated in R13).
__device__ __forceinline__ float gelu_fast(float v) {
    float x = fabsf(v) * 0.70710678118654752f;
    float p = 1.0f + x * (0.0705230784f + x * (0.0422820123f
            + x * (0.0092705272f + x * (0.0001520143f
            + x * (0.0002765672f + x * 0.0000430638f)))));
    float p2 = p * p;
    float p4 = p2 * p2;
    float p8 = p4 * p4;
    float p16 = p8 * p8;
    float erf;
    asm("rcp.approx.f32 %0, %1;" : "=f"(erf) : "f"(p16));
    erf = 1.0f - erf;
    float cdf = fmaf(copysignf(erf, v), 0.5f, 0.5f);
    return v * cdf;
}

__device__ __forceinline__ uint32_t pk(__half a, __half b) {
    return (uint32_t)__half_as_ushort(a) | ((uint32_t)__half_as_ushort(b) << 16);
}

// ============================================================================
// merged prepass (R13 + __ldcs evict-first input reads)
// ============================================================================
__device__ __forceinline__ void conv_w_tile(const float* __restrict__ we,
                                            __half* __restrict__ oe,
                                            float (*t)[65],
                                            int K, int N, int kb, int nb,
                                            int tid) {
    {
        const int r = tid >> 3;
        const int c0 = (tid & 7) * 8;
        const float* src = we + (size_t)(kb + r) * N + nb + c0;
        float4 v0 = __ldcs((const float4*)src);
        float4 v1 = __ldcs((const float4*)(src + 4));
        t[r][c0 + 0] = v0.x; t[r][c0 + 1] = v0.y; t[r][c0 + 2] = v0.z; t[r][c0 + 3] = v0.w;
        t[r][c0 + 4] = v1.x; t[r][c0 + 5] = v1.y; t[r][c0 + 6] = v1.z; t[r][c0 + 7] = v1.w;
    }
    __syncthreads();
    {
        const int nloc = tid >> 2;
        const int kq = (tid & 3) * 8;
        uint32_t o[4];
        #pragma unroll
        for (int j = 0; j < 4; j++)
            o[j] = pk(__float2half_rn(t[kq + 2 * j][nloc]),
                      __float2half_rn(t[kq + 2 * j + 1][nloc]));
        *(uint4*)(oe + (size_t)(nb + nloc) * K + kb + kq) =
            make_uint4(o[0], o[1], o[2], o[3]);
    }
    __syncthreads();
}

__global__ void prepass(const float* __restrict__ x,
                        const float* __restrict__ w1,
                        const float* __restrict__ w2,
                        __half* __restrict__ x2,
                        __half* __restrict__ w1t,
                        __half* __restrict__ w2t)
{
    __shared__ float t[32][65];
    const int bid = blockIdx.x;
    const int tid = threadIdx.x;

    if (bid < 16384) {
        size_t base = ((size_t)bid * 256 + tid) * 8;
        float4 v0 = __ldcs((const float4*)(x + base));
        float4 v1 = __ldcs((const float4*)(x + base + 4));
        uint4 o;
        o.x = pk(__float2half_rn(v0.x), __float2half_rn(v0.y));
        o.y = pk(__float2half_rn(v0.z), __float2half_rn(v0.w));
        o.z = pk(__float2half_rn(v1.x), __float2half_rn(v1.y));
        o.w = pk(__float2half_rn(v1.z), __float2half_rn(v1.w));
        *(uint4*)(x2 + base) = o;
    } else if (bid < 24576) {
        const int rem = bid - 16384;
        const int e = rem >> 10;
        const int within = rem & 1023;
        const int kb = (within & 31) * 32;
        const int nb = (within >> 5) * 64;
        conv_w_tile(w1 + (size_t)e * D_ * H_, w1t + (size_t)e * H_ * D_,
                    t, D_, H_, kb, nb, tid);
    } else {
        const int rem = bid - 24576;
        const int e = rem >> 10;
        const int within = rem & 1023;
        const int kb = (within & 63) * 32;
        const int nb = (within >> 6) * 64;
        conv_w_tile(w2 + (size_t)e * H_ * D_, w2t + (size_t)e * D_ * H_,
                    t, H_, D_, kb, nb, tid);
    }
}

// ============================================================================
// GEMM: C tile 128x256, warp 64x64, k64 chunks, 4-stage cp.async, 1 CTA/SM.
// Loop cadence identical to R13; fills get one extra chunk of latency slack.
// ============================================================================
template <int EPI, int KR>
__global__ __launch_bounds__(256, 1)
void gemm_mma(const __half* __restrict__ A,
              const __half* __restrict__ B,
              const float* __restrict__ bias,
              float* __restrict__ OutF,
              __half* __restrict__ OutH,
              int NBtot)
{
    extern __shared__ __align__(1024) char sm[];
    __shared__ float s_bias[256];

    constexpr int NC = KR / 64;
    constexpr size_t gStride = (size_t)64 * KR;

    const int tid = threadIdx.x;
    const int wid = tid >> 5;
    const int lid = tid & 31;
    const int warp_m = wid >> 2;
    const int warp_n = wid & 3;
    const int e = blockIdx.z;
    const int rowBase = blockIdx.y * 128;
    const int colBase = blockIdx.x * 256;
    const size_t rowGlob0 = (size_t)e * T_ + rowBase;
    const uint32_t smb = smem_u32(sm);

    s_bias[tid] = bias[(size_t)e * NBtot + colBase + tid];

    const int r0 = tid >> 3, g0 = tid & 7;
    const char* aCur = (const char*)(A + (rowGlob0 + r0) * (size_t)KR) + g0 * 16;
    const char* bCur = (const char*)(B + ((size_t)e * NBtot + colBase + r0) * (size_t)KR) + g0 * 16;
    const uint32_t sO0 = (uint32_t)(r0 * 128 + ((g0 << 4) ^ ((r0 & 7) << 4)));

    const int lr = (lid & 7) + ((lid >> 3) & 1) * 8;
    const uint32_t lcol = ((lid >> 4) & 1) << 4;
    const uint32_t xr = (uint32_t)(lr & 7) << 4;
    const uint32_t arb0 = (uint32_t)(warp_m * 64 + lr) * 128;
    const uint32_t brb0 = (uint32_t)(warp_n * 64 + lr) * 128 + A_BYTES;

    uint32_t colq[4];
    #pragma unroll
    for (int q = 0; q < 4; q++) colq[q] = ((uint32_t)(q << 5) | lcol) ^ xr;

    float acc[4][8][4];
    #pragma unroll
    for (int m = 0; m < 4; m++)
        #pragma unroll
        for (int n = 0; n < 8; n++)
            #pragma unroll
            for (int q = 0; q < 4; q++)
                acc[m][n][q] = 0.0f;

    auto fill = [&](uint32_t sbase) {
        uint32_t sb = sbase + sO0;
        #pragma unroll
        for (int i = 0; i < 4; i++)
            cpa16(sb + i * 4096, aCur + i * gStride);
        #pragma unroll
        for (int i = 0; i < 8; i++)
            cpa16(sb + A_BYTES + i * 4096, bCur + i * gStride);
        asm volatile("cp.async.commit_group;" ::: "memory");
        aCur += 128; bCur += 128;
    };
    auto commit_empty = [&]() {
        asm volatile("cp.async.commit_group;" ::: "memory");
    };

    auto ldA = [&](uint32_t st, uint32_t col, uint32_t (&fr)[4][4]) {
        #pragma unroll
        for (int f = 0; f < 4; f++)
            ldsm_x4(fr[f], st + arb0 + f * 2048 + col);
    };
    auto ldB = [&](uint32_t st, uint32_t col, uint32_t (&fr)[4][4]) {
        #pragma unroll
        for (int g = 0; g < 4; g++)
            ldsm_x4(fr[g], st + brb0 + g * 2048 + col);
    };
    auto mmaT = [&](const uint32_t (&a)[4][4], const uint32_t (&b)[4][4]) {
        #pragma unroll
        for (int m = 0; m < 4; m++)
            #pragma unroll
            for (int n = 0; n < 8; n++)
                mma_f16(acc[m][n], a[m], b[n >> 1][n & 1], b[n >> 1][2 + (n & 1)]);
    };

    // prologue: fill all 4 stages (chunks 0..3)
    uint32_t st0 = smb, st1 = smb + STAGE, st2 = smb + 2 * STAGE, st3 = smb + 3 * STAGE;
    fill(st0); fill(st1); fill(st2); fill(st3);
    asm volatile("cp.async.wait_group 3;" ::: "memory");   // chunk 0 ready
    __syncthreads();

    uint32_t aF[2][4][4], bF[2][4][4];
    ldA(st0, colq[0], aF[0]);
    ldB(st0, colq[0], bF[0]);

    #pragma unroll 1
    for (int c = 0; c < NC - 1; c++) {
        const uint32_t st = st0;

        ldA(st, colq[1], aF[1]);
        ldB(st, colq[1], bF[1]);
        mmaT(aF[0], bF[0]);                // q0

        ldA(st, colq[2], aF[0]);
        ldB(st, colq[2], bF[0]);
        mmaT(aF[1], bF[1]);                // q1

        ldA(st, colq[3], aF[1]);
        ldB(st, colq[3], bF[1]);
        mmaT(aF[0], bF[0]);                // q2

        // wait_group 2: chunks <= c+1 complete (c+2, c+3 may be in flight).
        asm volatile("cp.async.wait_group 2;" ::: "memory");
        __syncthreads();
        if (c + 4 < NC) fill(st); else commit_empty();   // chunk c+4 -> stage just consumed

        ldA(st1, colq[0], aF[0]);          // next chunk q0 prefetch (chunk c+1)
        mmaT(aF[1], bF[1]);                // q3 (register-only, hides barrier)
        ldB(st1, colq[0], bF[0]);

        uint32_t t = st0; st0 = st1; st1 = st2; st2 = st3; st3 = t;
    }

    // final chunk
    {
        const uint32_t st = st0;
        ldA(st, colq[1], aF[1]);
        ldB(st, colq[1], bF[1]);
        mmaT(aF[0], bF[0]);
        ldA(st, colq[2], aF[0]);
        ldB(st, colq[2], bF[0]);
        mmaT(aF[1], bF[1]);
        ldA(st, colq[3], aF[1]);
        ldB(st, colq[3], bF[1]);
        mmaT(aF[0], bF[0]);
        mmaT(aF[1], bF[1]);
    }
    __syncthreads();

    // ---- epilogue ----
    #pragma unroll
    for (int m = 0; m < 4; m++) {
        const size_t rG = rowGlob0 + warp_m * 64 + m * 16 + (lid >> 2);
        #pragma unroll
        for (int n = 0; n < 8; n++) {
            const int cl = warp_n * 64 + n * 8 + (lid & 3) * 2;
            const float b0 = s_bias[cl], b1 = s_bias[cl + 1];
            const int cg = colBase + cl;
            #pragma unroll
            for (int h = 0; h < 2; h++) {
                float v0 = acc[m][n][2 * h + 0] + b0;
                float v1 = acc[m][n][2 * h + 1] + b1;
                const size_t rr = rG + h * 8;
                if (EPI == 1) {
                    v0 = gelu_fast(v0); v1 = gelu_fast(v1);
                    *(uint32_t*)(OutH + rr * (size_t)NBtot + cg) =
                        pk(__float2half_rn(v0), __float2half_rn(v1));
                } else {
                    // out is never re-read: streaming store, keep L2 for h2/w2t
                    asm volatile("st.global.cs.v2.f32 [%0], {%1, %2};"
                                 :: "l"(OutF + rr * (size_t)NBtot + cg),
                                    "f"(v0), "f"(v1) : "memory");
                }
            }
        }
    }
}

// ============================================================================
extern "C" void kernel_launch(void* const* d_in, const int* in_sizes, int n_in,
                              void* d_out, int out_size)
{
    (void)in_sizes; (void)n_in; (void)out_size;
    const float* x  = (const float*)d_in[0];
    const float* w1 = (const float*)d_in[1];
    const float* b1 = (const float*)d_in[2];
    const float* w2 = (const float*)d_in[3];
    const float* b2 = (const float*)d_in[4];
    float* out = (float*)d_out;

    __half *x2, *w1t, *h2, *w2t;
    cudaGetSymbolAddress((void**)&x2,  g_x2);
    cudaGetSymbolAddress((void**)&w1t, g_w1t);
    cudaGetSymbolAddress((void**)&h2,  g_h2);
    cudaGetSymbolAddress((void**)&w2t, g_w2t);

    const int SMEM = NSTAGE * STAGE;   // 196608
    cudaFuncSetAttribute((const void*)gemm_mma<1, D_>,
                         cudaFuncAttributeMaxDynamicSharedMemorySize, SMEM);
    cudaFuncSetAttribute((const void*)gemm_mma<0, H_>,
                         cudaFuncAttributeMaxDynamicSharedMemorySize, SMEM);

    // merged prepass
    prepass<<<32768, 256>>>(x, w1, w2, x2, w1t, w2t);

    // GEMM1: K=1024, tiles 128x256 over N=2048
    gemm_mma<1, D_><<<dim3(H_ / 256, T_ / 128, E_), 256, SMEM>>>(
        x2, w1t, b1, nullptr, h2, H_);

    // GEMM2: K=2048, tiles 128x256 over N=1024
    gemm_mma<0, H_><<<dim3(D_ / 256, T_ / 128, E_), 256, SMEM>>>(
        h2, w2t, b2, out, nullptr, D_);
}

// round 16
// speedup vs baseline: 1.0118x; 1.0026x over previous
#include <cuda_runtime.h>
#include <cuda_fp16.h>
#include <cstdint>
#include <math.h>

// ============================================================================
// Experts MLP via plain fp16 mma.sync GEMMs (fp32 accumulate).
// R16 = R13 GEMM loop (byte-identical; measured best: 3-stage cp.async,
// 128x256 tile, warp 64x64, barrier per k64 chunk, plain stores)
//     + R15 prepass (__ldcs evict-first input reads; measured 58.5us).
// ============================================================================

#define E_ 8
#define T_ 4096
#define D_ 1024
#define H_ 2048

#define A_BYTES 16384              // 128 rows * 128B
#define STAGE   49152              // A(16K) + B(32K)
#define NSTAGE  3

__device__ __align__(256) __half g_x2[(size_t)32768 * 1024];
__device__ __align__(256) __half g_w1t[(size_t)8 * 2048 * 1024];
__device__ __align__(256) __half g_h2[(size_t)32768 * 2048];
__device__ __align__(256) __half g_w2t[(size_t)8 * 1024 * 2048];

__device__ __forceinline__ uint32_t smem_u32(const void* p) {
    uint32_t a;
    asm("{ .reg .u64 t; cvta.to.shared.u64 t, %1; cvt.u32.u64 %0, t; }"
        : "=r"(a) : "l"(p));
    return a;
}
__device__ __forceinline__ void cpa16(uint32_t dst, const void* src) {
    asm volatile("cp.async.cg.shared.global [%0], [%1], 16;" :: "r"(dst), "l"(src));
}
__device__ __forceinline__ void ldsm_x4(uint32_t* r, uint32_t addr) {
    asm volatile("ldmatrix.sync.aligned.m8n8.x4.shared.b16 {%0,%1,%2,%3}, [%4];"
                 : "=r"(r[0]), "=r"(r[1]), "=r"(r[2]), "=r"(r[3]) : "r"(addr));
}
__device__ __forceinline__ void mma_f16(float* c, const uint32_t* a,
                                        uint32_t b0, uint32_t b1) {
    asm volatile(
        "mma.sync.aligned.m16n8k16.row.col.f32.f16.f16.f32 "
        "{%0,%1,%2,%3}, {%4,%5,%6,%7}, {%8,%9}, {%0,%1,%2,%3};"
        : "+f"(c[0]), "+f"(c[1]), "+f"(c[2]), "+f"(c[3])
        : "r"(a[0]), "r"(a[1]), "r"(a[2]), "r"(a[3]), "r"(b0), "r"(b1));
}

// Branchless GELU (A&S 7.1.28 erf approx; validated in R13).
__device__ __forceinline__ float gelu_fast(float v) {
    float x = fabsf(v) * 0.70710678118654752f;
    float p = 1.0f + x * (0.0705230784f + x * (0.0422820123f
            + x * (0.0092705272f + x * (0.0001520143f
            + x * (0.0002765672f + x * 0.0000430638f)))));
    float p2 = p * p;
    float p4 = p2 * p2;
    float p8 = p4 * p4;
    float p16 = p8 * p8;
    float erf;
    asm("rcp.approx.f32 %0, %1;" : "=f"(erf) : "f"(p16));
    erf = 1.0f - erf;
    float cdf = fmaf(copysignf(erf, v), 0.5f, 0.5f);
    return v * cdf;
}

__device__ __forceinline__ uint32_t pk(__half a, __half b) {
    return (uint32_t)__half_as_ushort(a) | ((uint32_t)__half_as_ushort(b) << 16);
}

// ============================================================================
// merged prepass (R15: __ldcs evict-first input reads)
// ============================================================================
__device__ __forceinline__ void conv_w_tile(const float* __restrict__ we,
                                            __half* __restrict__ oe,
                                            float (*t)[65],
                                            int K, int N, int kb, int nb,
                                            int tid) {
    {
        const int r = tid >> 3;
        const int c0 = (tid & 7) * 8;
        const float* src = we + (size_t)(kb + r) * N + nb + c0;
        float4 v0 = __ldcs((const float4*)src);
        float4 v1 = __ldcs((const float4*)(src + 4));
        t[r][c0 + 0] = v0.x; t[r][c0 + 1] = v0.y; t[r][c0 + 2] = v0.z; t[r][c0 + 3] = v0.w;
        t[r][c0 + 4] = v1.x; t[r][c0 + 5] = v1.y; t[r][c0 + 6] = v1.z; t[r][c0 + 7] = v1.w;
    }
    __syncthreads();
    {
        const int nloc = tid >> 2;
        const int kq = (tid & 3) * 8;
        uint32_t o[4];
        #pragma unroll
        for (int j = 0; j < 4; j++)
            o[j] = pk(__float2half_rn(t[kq + 2 * j][nloc]),
                      __float2half_rn(t[kq + 2 * j + 1][nloc]));
        *(uint4*)(oe + (size_t)(nb + nloc) * K + kb + kq) =
            make_uint4(o[0], o[1], o[2], o[3]);
    }
    __syncthreads();
}

__global__ void prepass(const float* __restrict__ x,
                        const float* __restrict__ w1,
                        const float* __restrict__ w2,
                        __half* __restrict__ x2,
                        __half* __restrict__ w1t,
                        __half* __restrict__ w2t)
{
    __shared__ float t[32][65];
    const int bid = blockIdx.x;
    const int tid = threadIdx.x;

    if (bid < 16384) {
        size_t base = ((size_t)bid * 256 + tid) * 8;
        float4 v0 = __ldcs((const float4*)(x + base));
        float4 v1 = __ldcs((const float4*)(x + base + 4));
        uint4 o;
        o.x = pk(__float2half_rn(v0.x), __float2half_rn(v0.y));
        o.y = pk(__float2half_rn(v0.z), __float2half_rn(v0.w));
        o.z = pk(__float2half_rn(v1.x), __float2half_rn(v1.y));
        o.w = pk(__float2half_rn(v1.z), __float2half_rn(v1.w));
        *(uint4*)(x2 + base) = o;
    } else if (bid < 24576) {
        const int rem = bid - 16384;
        const int e = rem >> 10;
        const int within = rem & 1023;
        const int kb = (within & 31) * 32;
        const int nb = (within >> 5) * 64;
        conv_w_tile(w1 + (size_t)e * D_ * H_, w1t + (size_t)e * H_ * D_,
                    t, D_, H_, kb, nb, tid);
    } else {
        const int rem = bid - 24576;
        const int e = rem >> 10;
        const int within = rem & 1023;
        const int kb = (within & 63) * 32;
        const int nb = (within >> 6) * 64;
        conv_w_tile(w2 + (size_t)e * H_ * D_, w2t + (size_t)e * D_ * H_,
                    t, H_, D_, kb, nb, tid);
    }
}

// ============================================================================
// GEMM: C tile 128x256, warp 64x64, k64 chunks, 3-stage cp.async, 1 CTA/SM.
// (R13 loop, byte-identical.)
// ============================================================================
template <int EPI, int KR>
__global__ __launch_bounds__(256, 1)
void gemm_mma(const __half* __restrict__ A,
              const __half* __restrict__ B,
              const float* __restrict__ bias,
              float* __restrict__ OutF,
              __half* __restrict__ OutH,
              int NBtot)
{
    extern __shared__ __align__(1024) char sm[];
    __shared__ float s_bias[256];

    constexpr int NC = KR / 64;
    constexpr size_t gStride = (size_t)64 * KR;

    const int tid = threadIdx.x;
    const int wid = tid >> 5;
    const int lid = tid & 31;
    const int warp_m = wid >> 2;
    const int warp_n = wid & 3;
    const int e = blockIdx.z;
    const int rowBase = blockIdx.y * 128;
    const int colBase = blockIdx.x * 256;
    const size_t rowGlob0 = (size_t)e * T_ + rowBase;
    const uint32_t smb = smem_u32(sm);

    s_bias[tid] = bias[(size_t)e * NBtot + colBase + tid];

    const int r0 = tid >> 3, g0 = tid & 7;
    const char* aCur = (const char*)(A + (rowGlob0 + r0) * (size_t)KR) + g0 * 16;
    const char* bCur = (const char*)(B + ((size_t)e * NBtot + colBase + r0) * (size_t)KR) + g0 * 16;
    const uint32_t sO0 = (uint32_t)(r0 * 128 + ((g0 << 4) ^ ((r0 & 7) << 4)));

    const int lr = (lid & 7) + ((lid >> 3) & 1) * 8;
    const uint32_t lcol = ((lid >> 4) & 1) << 4;
    const uint32_t xr = (uint32_t)(lr & 7) << 4;
    const uint32_t arb0 = (uint32_t)(warp_m * 64 + lr) * 128;
    const uint32_t brb0 = (uint32_t)(warp_n * 64 + lr) * 128 + A_BYTES;

    uint32_t colq[4];
    #pragma unroll
    for (int q = 0; q < 4; q++) colq[q] = ((uint32_t)(q << 5) | lcol) ^ xr;

    float acc[4][8][4];
    #pragma unroll
    for (int m = 0; m < 4; m++)
        #pragma unroll
        for (int n = 0; n < 8; n++)
            #pragma unroll
            for (int q = 0; q < 4; q++)
                acc[m][n][q] = 0.0f;

    auto fill = [&](uint32_t sbase) {
        uint32_t sb = sbase + sO0;
        #pragma unroll
        for (int i = 0; i < 4; i++)
            cpa16(sb + i * 4096, aCur + i * gStride);
        #pragma unroll
        for (int i = 0; i < 8; i++)
            cpa16(sb + A_BYTES + i * 4096, bCur + i * gStride);
        asm volatile("cp.async.commit_group;" ::: "memory");
        aCur += 128; bCur += 128;
    };
    auto commit_empty = [&]() {
        asm volatile("cp.async.commit_group;" ::: "memory");
    };

    auto ldA = [&](uint32_t st, uint32_t col, uint32_t (&fr)[4][4]) {
        #pragma unroll
        for (int f = 0; f < 4; f++)
            ldsm_x4(fr[f], st + arb0 + f * 2048 + col);
    };
    auto ldB = [&](uint32_t st, uint32_t col, uint32_t (&fr)[4][4]) {
        #pragma unroll
        for (int g = 0; g < 4; g++)
            ldsm_x4(fr[g], st + brb0 + g * 2048 + col);
    };
    auto mmaT = [&](const uint32_t (&a)[4][4], const uint32_t (&b)[4][4]) {
        #pragma unroll
        for (int m = 0; m < 4; m++)
            #pragma unroll
            for (int n = 0; n < 8; n++)
                mma_f16(acc[m][n], a[m], b[n >> 1][n & 1], b[n >> 1][2 + (n & 1)]);
    };

    // prologue
    uint32_t st0 = smb, st1 = smb + STAGE, st2 = smb + 2 * STAGE;
    fill(st0); fill(st1); fill(st2);
    asm volatile("cp.async.wait_group 2;" ::: "memory");
    __syncthreads();

    uint32_t aF[2][4][4], bF[2][4][4];
    ldA(st0, colq[0], aF[0]);
    ldB(st0, colq[0], bF[0]);

    #pragma unroll 1
    for (int c = 0; c < NC - 1; c++) {
        const uint32_t st = st0;

        ldA(st, colq[1], aF[1]);
        ldB(st, colq[1], bF[1]);
        mmaT(aF[0], bF[0]);                // q0

        ldA(st, colq[2], aF[0]);
        ldB(st, colq[2], bF[0]);
        mmaT(aF[1], bF[1]);                // q1

        ldA(st, colq[3], aF[1]);
        ldB(st, colq[3], bF[1]);
        mmaT(aF[0], bF[0]);                // q2

        asm volatile("cp.async.wait_group 1;" ::: "memory");
        __syncthreads();
        if (c + 3 < NC) fill(st); else commit_empty();

        ldA(st1, colq[0], aF[0]);          // next chunk q0 prefetch
        mmaT(aF[1], bF[1]);                // q3 (register-only, hides barrier)
        ldB(st1, colq[0], bF[0]);

        uint32_t t = st0; st0 = st1; st1 = st2; st2 = t;
    }

    // final chunk
    {
        const uint32_t st = st0;
        ldA(st, colq[1], aF[1]);
        ldB(st, colq[1], bF[1]);
        mmaT(aF[0], bF[0]);
        ldA(st, colq[2], aF[0]);
        ldB(st, colq[2], bF[0]);
        mmaT(aF[1], bF[1]);
        ldA(st, colq[3], aF[1]);
        ldB(st, colq[3], bF[1]);
        mmaT(aF[0], bF[0]);
        mmaT(aF[1], bF[1]);
    }
    __syncthreads();

    // ---- epilogue ----
    #pragma unroll
    for (int m = 0; m < 4; m++) {
        const size_t rG = rowGlob0 + warp_m * 64 + m * 16 + (lid >> 2);
        #pragma unroll
        for (int n = 0; n < 8; n++) {
            const int cl = warp_n * 64 + n * 8 + (lid & 3) * 2;
            const float b0 = s_bias[cl], b1 = s_bias[cl + 1];
            const int cg = colBase + cl;
            #pragma unroll
            for (int h = 0; h < 2; h++) {
                float v0 = acc[m][n][2 * h + 0] + b0;
                float v1 = acc[m][n][2 * h + 1] + b1;
                const size_t rr = rG + h * 8;
                if (EPI == 1) {
                    v0 = gelu_fast(v0); v1 = gelu_fast(v1);
                    *(uint32_t*)(OutH + rr * (size_t)NBtot + cg) =
                        pk(__float2half_rn(v0), __float2half_rn(v1));
                } else {
                    *(float2*)(OutF + rr * (size_t)NBtot + cg) = make_float2(v0, v1);
                }
            }
        }
    }
}

// ============================================================================
extern "C" void kernel_launch(void* const* d_in, const int* in_sizes, int n_in,
                              void* d_out, int out_size)
{
    (void)in_sizes; (void)n_in; (void)out_size;
    const float* x  = (const float*)d_in[0];
    const float* w1 = (const float*)d_in[1];
    const float* b1 = (const float*)d_in[2];
    const float* w2 = (const float*)d_in[3];
    const float* b2 = (const float*)d_in[4];
    float* out = (float*)d_out;

    __half *x2, *w1t, *h2, *w2t;
    cudaGetSymbolAddress((void**)&x2,  g_x2);
    cudaGetSymbolAddress((void**)&w1t, g_w1t);
    cudaGetSymbolAddress((void**)&h2,  g_h2);
    cudaGetSymbolAddress((void**)&w2t, g_w2t);

    const int SMEM = NSTAGE * STAGE;   // 147456
    cudaFuncSetAttribute((const void*)gemm_mma<1, D_>,
                         cudaFuncAttributeMaxDynamicSharedMemorySize, SMEM);
    cudaFuncSetAttribute((const void*)gemm_mma<0, H_>,
                         cudaFuncAttributeMaxDynamicSharedMemorySize, SMEM);

    // merged prepass
    prepass<<<32768, 256>>>(x, w1, w2, x2, w1t, w2t);

    // GEMM1: K=1024, tiles 128x256 over N=2048
    gemm_mma<1, D_><<<dim3(H_ / 256, T_ / 128, E_), 256, SMEM>>>(
        x2, w1t, b1, nullptr, h2, H_);

    // GEMM2: K=2048, tiles 128x256 over N=1024
    gemm_mma<0, H_><<<dim3(D_ / 256, T_ / 128, E_), 256, SMEM>>>(
        h2, w2t, b2, out, nullptr, D_);
}

// round 17
// speedup vs baseline: 1.0149x; 1.0031x over previous
#include <cuda_runtime.h>
#include <cuda_fp16.h>
#include <cstdint>
#include <math.h>

// ============================================================================
// Experts MLP via plain fp16 mma.sync GEMMs (fp32 accumulate).
// R17 = R16 champion + reversed tile order in GEMM2 (LIFO h2 consumption:
// GEMM2 starts on the h2 region GEMM1 wrote last -> still L2-resident).
// ============================================================================

#define E_ 8
#define T_ 4096
#define D_ 1024
#define H_ 2048

#define A_BYTES 16384              // 128 rows * 128B
#define STAGE   49152              // A(16K) + B(32K)
#define NSTAGE  3

__device__ __align__(256) __half g_x2[(size_t)32768 * 1024];
__device__ __align__(256) __half g_w1t[(size_t)8 * 2048 * 1024];
__device__ __align__(256) __half g_h2[(size_t)32768 * 2048];
__device__ __align__(256) __half g_w2t[(size_t)8 * 1024 * 2048];

__device__ __forceinline__ uint32_t smem_u32(const void* p) {
    uint32_t a;
    asm("{ .reg .u64 t; cvta.to.shared.u64 t, %1; cvt.u32.u64 %0, t; }"
        : "=r"(a) : "l"(p));
    return a;
}
__device__ __forceinline__ void cpa16(uint32_t dst, const void* src) {
    asm volatile("cp.async.cg.shared.global [%0], [%1], 16;" :: "r"(dst), "l"(src));
}
__device__ __forceinline__ void ldsm_x4(uint32_t* r, uint32_t addr) {
    asm volatile("ldmatrix.sync.aligned.m8n8.x4.shared.b16 {%0,%1,%2,%3}, [%4];"
                 : "=r"(r[0]), "=r"(r[1]), "=r"(r[2]), "=r"(r[3]) : "r"(addr));
}
__device__ __forceinline__ void mma_f16(float* c, const uint32_t* a,
                                        uint32_t b0, uint32_t b1) {
    asm volatile(
        "mma.sync.aligned.m16n8k16.row.col.f32.f16.f16.f32 "
        "{%0,%1,%2,%3}, {%4,%5,%6,%7}, {%8,%9}, {%0,%1,%2,%3};"
        : "+f"(c[0]), "+f"(c[1]), "+f"(c[2]), "+f"(c[3])
        : "r"(a[0]), "r"(a[1]), "r"(a[2]), "r"(a[3]), "r"(b0), "r"(b1));
}

// Branchless GELU (A&S 7.1.28 erf approx; validated in R13).
__device__ __forceinline__ float gelu_fast(float v) {
    float x = fabsf(v) * 0.70710678118654752f;
    float p = 1.0f + x * (0.0705230784f + x * (0.0422820123f
            + x * (0.0092705272f + x * (0.0001520143f
            + x * (0.0002765672f + x * 0.0000430638f)))));
    float p2 = p * p;
    float p4 = p2 * p2;
    float p8 = p4 * p4;
    float p16 = p8 * p8;
    float erf;
    asm("rcp.approx.f32 %0, %1;" : "=f"(erf) : "f"(p16));
    erf = 1.0f - erf;
    float cdf = fmaf(copysignf(erf, v), 0.5f, 0.5f);
    return v * cdf;
}

__device__ __forceinline__ uint32_t pk(__half a, __half b) {
    return (uint32_t)__half_as_ushort(a) | ((uint32_t)__half_as_ushort(b) << 16);
}

// ============================================================================
// merged prepass (R15/R16: __ldcs evict-first input reads)
// ============================================================================
__device__ __forceinline__ void conv_w_tile(const float* __restrict__ we,
                                            __half* __restrict__ oe,
                                            float (*t)[65],
                                            int K, int N, int kb, int nb,
                                            int tid) {
    {
        const int r = tid >> 3;
        const int c0 = (tid & 7) * 8;
        const float* src = we + (size_t)(kb + r) * N + nb + c0;
        float4 v0 = __ldcs((const float4*)src);
        float4 v1 = __ldcs((const float4*)(src + 4));
        t[r][c0 + 0] = v0.x; t[r][c0 + 1] = v0.y; t[r][c0 + 2] = v0.z; t[r][c0 + 3] = v0.w;
        t[r][c0 + 4] = v1.x; t[r][c0 + 5] = v1.y; t[r][c0 + 6] = v1.z; t[r][c0 + 7] = v1.w;
    }
    __syncthreads();
    {
        const int nloc = tid >> 2;
        const int kq = (tid & 3) * 8;
        uint32_t o[4];
        #pragma unroll
        for (int j = 0; j < 4; j++)
            o[j] = pk(__float2half_rn(t[kq + 2 * j][nloc]),
                      __float2half_rn(t[kq + 2 * j + 1][nloc]));
        *(uint4*)(oe + (size_t)(nb + nloc) * K + kb + kq) =
            make_uint4(o[0], o[1], o[2], o[3]);
    }
    __syncthreads();
}

__global__ void prepass(const float* __restrict__ x,
                        const float* __restrict__ w1,
                        const float* __restrict__ w2,
                        __half* __restrict__ x2,
                        __half* __restrict__ w1t,
                        __half* __restrict__ w2t)
{
    __shared__ float t[32][65];
    const int bid = blockIdx.x;
    const int tid = threadIdx.x;

    if (bid < 16384) {
        size_t base = ((size_t)bid * 256 + tid) * 8;
        float4 v0 = __ldcs((const float4*)(x + base));
        float4 v1 = __ldcs((const float4*)(x + base + 4));
        uint4 o;
        o.x = pk(__float2half_rn(v0.x), __float2half_rn(v0.y));
        o.y = pk(__float2half_rn(v0.z), __float2half_rn(v0.w));
        o.z = pk(__float2half_rn(v1.x), __float2half_rn(v1.y));
        o.w = pk(__float2half_rn(v1.z), __float2half_rn(v1.w));
        *(uint4*)(x2 + base) = o;
    } else if (bid < 24576) {
        const int rem = bid - 16384;
        const int e = rem >> 10;
        const int within = rem & 1023;
        const int kb = (within & 31) * 32;
        const int nb = (within >> 5) * 64;
        conv_w_tile(w1 + (size_t)e * D_ * H_, w1t + (size_t)e * H_ * D_,
                    t, D_, H_, kb, nb, tid);
    } else {
        const int rem = bid - 24576;
        const int e = rem >> 10;
        const int within = rem & 1023;
        const int kb = (within & 63) * 32;
        const int nb = (within >> 6) * 64;
        conv_w_tile(w2 + (size_t)e * H_ * D_, w2t + (size_t)e * D_ * H_,
                    t, H_, D_, kb, nb, tid);
    }
}

// ============================================================================
// GEMM: C tile 128x256, warp 64x64, k64 chunks, 3-stage cp.async, 1 CTA/SM.
// REV=1 reverses the block->tile map (expert + row tile) for LIFO h2 reads.
// Loop is byte-identical to the R13/R16 champion.
// ============================================================================
template <int EPI, int KR, int REV>
__global__ __launch_bounds__(256, 1)
void gemm_mma(const __half* __restrict__ A,
              const __half* __restrict__ B,
              const float* __restrict__ bias,
              float* __restrict__ OutF,
              __half* __restrict__ OutH,
              int NBtot)
{
    extern __shared__ __align__(1024) char sm[];
    __shared__ float s_bias[256];

    constexpr int NC = KR / 64;
    constexpr size_t gStride = (size_t)64 * KR;

    const int tid = threadIdx.x;
    const int wid = tid >> 5;
    const int lid = tid & 31;
    const int warp_m = wid >> 2;
    const int warp_n = wid & 3;
    const int e = REV ? (int)(gridDim.z - 1 - blockIdx.z) : (int)blockIdx.z;
    const int by = REV ? (int)(gridDim.y - 1 - blockIdx.y) : (int)blockIdx.y;
    const int rowBase = by * 128;
    const int colBase = blockIdx.x * 256;
    const size_t rowGlob0 = (size_t)e * T_ + rowBase;
    const uint32_t smb = smem_u32(sm);

    s_bias[tid] = bias[(size_t)e * NBtot + colBase + tid];

    const int r0 = tid >> 3, g0 = tid & 7;
    const char* aCur = (const char*)(A + (rowGlob0 + r0) * (size_t)KR) + g0 * 16;
    const char* bCur = (const char*)(B + ((size_t)e * NBtot + colBase + r0) * (size_t)KR) + g0 * 16;
    const uint32_t sO0 = (uint32_t)(r0 * 128 + ((g0 << 4) ^ ((r0 & 7) << 4)));

    const int lr = (lid & 7) + ((lid >> 3) & 1) * 8;
    const uint32_t lcol = ((lid >> 4) & 1) << 4;
    const uint32_t xr = (uint32_t)(lr & 7) << 4;
    const uint32_t arb0 = (uint32_t)(warp_m * 64 + lr) * 128;
    const uint32_t brb0 = (uint32_t)(warp_n * 64 + lr) * 128 + A_BYTES;

    uint32_t colq[4];
    #pragma unroll
    for (int q = 0; q < 4; q++) colq[q] = ((uint32_t)(q << 5) | lcol) ^ xr;

    float acc[4][8][4];
    #pragma unroll
    for (int m = 0; m < 4; m++)
        #pragma unroll
        for (int n = 0; n < 8; n++)
            #pragma unroll
            for (int q = 0; q < 4; q++)
                acc[m][n][q] = 0.0f;

    auto fill = [&](uint32_t sbase) {
        uint32_t sb = sbase + sO0;
        #pragma unroll
        for (int i = 0; i < 4; i++)
            cpa16(sb + i * 4096, aCur + i * gStride);
        #pragma unroll
        for (int i = 0; i < 8; i++)
            cpa16(sb + A_BYTES + i * 4096, bCur + i * gStride);
        asm volatile("cp.async.commit_group;" ::: "memory");
        aCur += 128; bCur += 128;
    };
    auto commit_empty = [&]() {
        asm volatile("cp.async.commit_group;" ::: "memory");
    };

    auto ldA = [&](uint32_t st, uint32_t col, uint32_t (&fr)[4][4]) {
        #pragma unroll
        for (int f = 0; f < 4; f++)
            ldsm_x4(fr[f], st + arb0 + f * 2048 + col);
    };
    auto ldB = [&](uint32_t st, uint32_t col, uint32_t (&fr)[4][4]) {
        #pragma unroll
        for (int g = 0; g < 4; g++)
            ldsm_x4(fr[g], st + brb0 + g * 2048 + col);
    };
    auto mmaT = [&](const uint32_t (&a)[4][4], const uint32_t (&b)[4][4]) {
        #pragma unroll
        for (int m = 0; m < 4; m++)
            #pragma unroll
            for (int n = 0; n < 8; n++)
                mma_f16(acc[m][n], a[m], b[n >> 1][n & 1], b[n >> 1][2 + (n & 1)]);
    };

    // prologue
    uint32_t st0 = smb, st1 = smb + STAGE, st2 = smb + 2 * STAGE;
    fill(st0); fill(st1); fill(st2);
    asm volatile("cp.async.wait_group 2;" ::: "memory");
    __syncthreads();

    uint32_t aF[2][4][4], bF[2][4][4];
    ldA(st0, colq[0], aF[0]);
    ldB(st0, colq[0], bF[0]);

    #pragma unroll 1
    for (int c = 0; c < NC - 1; c++) {
        const uint32_t st = st0;

        ldA(st, colq[1], aF[1]);
        ldB(st, colq[1], bF[1]);
        mmaT(aF[0], bF[0]);                // q0

        ldA(st, colq[2], aF[0]);
        ldB(st, colq[2], bF[0]);
        mmaT(aF[1], bF[1]);                // q1

        ldA(st, colq[3], aF[1]);
        ldB(st, colq[3], bF[1]);
        mmaT(aF[0], bF[0]);                // q2

        asm volatile("cp.async.wait_group 1;" ::: "memory");
        __syncthreads();
        if (c + 3 < NC) fill(st); else commit_empty();

        ldA(st1, colq[0], aF[0]);          // next chunk q0 prefetch
        mmaT(aF[1], bF[1]);                // q3 (register-only, hides barrier)
        ldB(st1, colq[0], bF[0]);

        uint32_t t = st0; st0 = st1; st1 = st2; st2 = t;
    }

    // final chunk
    {
        const uint32_t st = st0;
        ldA(st, colq[1], aF[1]);
        ldB(st, colq[1], bF[1]);
        mmaT(aF[0], bF[0]);
        ldA(st, colq[2], aF[0]);
        ldB(st, colq[2], bF[0]);
        mmaT(aF[1], bF[1]);
        ldA(st, colq[3], aF[1]);
        ldB(st, colq[3], bF[1]);
        mmaT(aF[0], bF[0]);
        mmaT(aF[1], bF[1]);
    }
    __syncthreads();

    // ---- epilogue ----
    #pragma unroll
    for (int m = 0; m < 4; m++) {
        const size_t rG = rowGlob0 + warp_m * 64 + m * 16 + (lid >> 2);
        #pragma unroll
        for (int n = 0; n < 8; n++) {
            const int cl = warp_n * 64 + n * 8 + (lid & 3) * 2;
            const float b0 = s_bias[cl], b1 = s_bias[cl + 1];
            const int cg = colBase + cl;
            #pragma unroll
            for (int h = 0; h < 2; h++) {
                float v0 = acc[m][n][2 * h + 0] + b0;
                float v1 = acc[m][n][2 * h + 1] + b1;
                const size_t rr = rG + h * 8;
                if (EPI == 1) {
                    v0 = gelu_fast(v0); v1 = gelu_fast(v1);
                    *(uint32_t*)(OutH + rr * (size_t)NBtot + cg) =
                        pk(__float2half_rn(v0), __float2half_rn(v1));
                } else {
                    *(float2*)(OutF + rr * (size_t)NBtot + cg) = make_float2(v0, v1);
                }
            }
        }
    }
}

// ============================================================================
extern "C" void kernel_launch(void* const* d_in, const int* in_sizes, int n_in,
                              void* d_out, int out_size)
{
    (void)in_sizes; (void)n_in; (void)out_size;
    const float* x  = (const float*)d_in[0];
    const float* w1 = (const float*)d_in[1];
    const float* b1 = (const float*)d_in[2];
    const float* w2 = (const float*)d_in[3];
    const float* b2 = (const float*)d_in[4];
    float* out = (float*)d_out;

    __half *x2, *w1t, *h2, *w2t;
    cudaGetSymbolAddress((void**)&x2,  g_x2);
    cudaGetSymbolAddress((void**)&w1t, g_w1t);
    cudaGetSymbolAddress((void**)&h2,  g_h2);
    cudaGetSymbolAddress((void**)&w2t, g_w2t);

    const int SMEM = NSTAGE * STAGE;   // 147456
    cudaFuncSetAttribute((const void*)gemm_mma<1, D_, 0>,
                         cudaFuncAttributeMaxDynamicSharedMemorySize, SMEM);
    cudaFuncSetAttribute((const void*)gemm_mma<0, H_, 1>,
                         cudaFuncAttributeMaxDynamicSharedMemorySize, SMEM);

    // merged prepass
    prepass<<<32768, 256>>>(x, w1, w2, x2, w1t, w2t);

    // GEMM1: K=1024, tiles 128x256 over N=2048 (forward order)
    gemm_mma<1, D_, 0><<<dim3(H_ / 256, T_ / 128, E_), 256, SMEM>>>(
        x2, w1t, b1, nullptr, h2, H_);

    // GEMM2: K=2048, tiles 128x256 over N=1024 (REVERSED tile order:
    // consume h2 LIFO so GEMM1's freshest output is read while L2-resident)
    gemm_mma<0, H_, 1><<<dim3(D_ / 256, T_ / 128, E_), 256, SMEM>>>(
        h2, w2t, b2, out, nullptr, D_);
}